// round 7
// baseline (speedup 1.0000x reference)
#include <cuda_runtime.h>
#include <math.h>

#define Nn 4096
#define Ee 8192
#define Mm 128
#define ND 128
#define ED 64
#define PQ 16
#define NP (Nn*PQ)
#define LAYERS 4
#define TAU 0.25f
#define FRIC 0.1f
#define MAXD 32
#define INC_CAP 16384
#define K4T 512
#define K4J 8      // nodes per thread = Nn / K4T
#define K4W (K4T/32)

// ---------------- device scratch (no allocation allowed) ----------------
__device__ float g_a[Nn], g_c[Nn], g_avt[Nn], g_avu[Nn];
__device__ float g_pd0[Nn], g_pwu[Nn], g_pn[Nn], g_qd0[Nn], g_Wn[Nn];
__device__ int   g_mol[Nn];
__device__ int   g_cnt[Nn];            // must be zero at k1 entry; reset in k5
__device__ int   g_adj[Nn * MAXD];     // (e<<12)|other
__device__ float g_winc[Nn * MAXD];    // per-slot edge weight
__device__ int   g_slotU[Ee], g_slotV[Ee];
__device__ float g_p0[NP], g_q0[NP];
__device__ float g_SA[Nn], g_SB[Nn], g_SC[Nn];

__device__ __forceinline__ float warp_sum(float v) {
#pragma unroll
    for (int o = 16; o; o >>= 1) v += __shfl_xor_sync(0xffffffffu, v, o);
    return v;
}
__device__ __forceinline__ float sigmoidf(float x) { return 1.f / (1.f + expf(-x)); }
__device__ __forceinline__ float softplusf(float x) { return fmaxf(x, 0.f) + log1pf(expf(-fabsf(x))); }

// ======== k1: node setup (warp/node) + mol ids + adjacency build ========
__global__ void k1(const float* __restrict__ vf, const float* __restrict__ mnm,
                   const int* __restrict__ us, const int* __restrict__ vs,
                   const float* __restrict__ We, const float* __restrict__ Wp,
                   const float* __restrict__ bp, const float* __restrict__ Wt,
                   const float* __restrict__ Wu)
{
    int tid  = blockIdx.x * blockDim.x + threadIdx.x;   // 131072 threads
    int lane = threadIdx.x & 31;
    int n    = tid >> 5;                                 // warp -> node

    if (tid < Nn) g_Wn[tid] = 0.f;

    for (int idx = tid; idx < Mm * Nn; idx += 131072)
        if (mnm[idx] > 0.5f) g_mol[idx & (Nn - 1)] = idx >> 12;

    for (int e = tid; e < Ee; e += 131072) {
        int u = us[e], v = vs[e];
        int s1 = atomicAdd(&g_cnt[u], 1);
        if (s1 < MAXD) g_adj[u * MAXD + s1] = (e << 12) | v;
        g_slotU[e] = s1;
        if (u != v) {
            int s2 = atomicAdd(&g_cnt[v], 1);
            if (s2 < MAXD) g_adj[v * MAXD + s2] = (e << 12) | u;
            g_slotV[e] = s2;
        }
    }

    float v0 = vf[n*ND+lane], v1 = vf[n*ND+lane+32], v2 = vf[n*ND+lane+64], v3 = vf[n*ND+lane+96];
    float sa = warp_sum(v0*We[lane]     + v1*We[lane+32]     + v2*We[lane+64]     + v3*We[lane+96]);
    float sc = warp_sum(v0*We[192+lane] + v1*We[192+lane+32] + v2*We[192+lane+64] + v3*We[192+lane+96]);
    float st = warp_sum(v0*Wt[lane]     + v1*Wt[lane+32]     + v2*Wt[lane+64]     + v3*Wt[lane+96]);
    float su = warp_sum(v0*Wu[lane]     + v1*Wu[lane+32]     + v2*Wu[lane+64]     + v3*Wu[lane+96]);

    float pk = 0.f;
#pragma unroll
    for (int k = 0; k < PQ; k++) {
        float s = warp_sum(v0*Wp[lane*PQ+k] + v1*Wp[(lane+32)*PQ+k] +
                           v2*Wp[(lane+64)*PQ+k] + v3*Wp[(lane+96)*PQ+k]);
        if (lane == k) pk = tanhf(s + bp[k]);
    }
    float pd0 = warp_sum(lane < PQ ? pk * Wt[ND+lane] : 0.f);
    float pwu = warp_sum(lane < PQ ? pk * Wu[ND+lane] : 0.f);
    float pn  = warp_sum(lane < PQ ? pk * pk          : 0.f);
    if (lane < PQ) g_p0[n*PQ+lane] = pk;
    if (lane == 0) {
        g_a[n] = sa; g_c[n] = sc; g_avt[n] = st; g_avu[n] = su;
        g_pd0[n] = pd0; g_pwu[n] = pwu; g_pn[n] = pn;
    }
}

// ======== k2: edge weights (warp/edge) ========
__global__ void k2(const float* __restrict__ ef,
                   const int* __restrict__ us, const int* __restrict__ vs,
                   const float* __restrict__ We, const float* __restrict__ be)
{
    int e    = (blockIdx.x * blockDim.x + threadIdx.x) >> 5;
    int lane = threadIdx.x & 31;
    if (e >= Ee) return;
    float s = ef[e*ED+lane] * We[128+lane] + ef[e*ED+32+lane] * We[160+lane];
    s = warp_sum(s);
    if (lane == 0) {
        int u = us[e], v = vs[e];
        float w = sigmoidf(g_a[u] + g_c[v] + s + be[0]);
        int s1 = g_slotU[e];
        if (s1 < MAXD) g_winc[u * MAXD + s1] = w;
        if (u != v) {
            int s2 = g_slotV[e];
            if (s2 < MAXD) g_winc[v * MAXD + s2] = w;
            atomicAdd(&g_Wn[u], w);
            atomicAdd(&g_Wn[v], w);
        }
    }
}

// ======== k3: q0 = tanh((e@v)@Wq + bq), qdot0 (warp/node) ========
__global__ void k3(const float* __restrict__ vf, const float* __restrict__ Wq,
                   const float* __restrict__ bq, const float* __restrict__ Wu)
{
    int n    = (blockIdx.x * blockDim.x + threadIdx.x) >> 5;
    int lane = threadIdx.x & 31;
    float x0 = vf[n*ND+lane], x1 = vf[n*ND+lane+32], x2 = vf[n*ND+lane+64], x3 = vf[n*ND+lane+96];
    float Wn = g_Wn[n];
    float e0 = Wn*x0, e1 = Wn*x1, e2 = Wn*x2, e3 = Wn*x3;
    int deg = min(g_cnt[n], MAXD);
    for (int j = 0; j < deg; j++) {
        int   o = g_adj[n*MAXD+j] & 0xFFF;
        float w = g_winc[n*MAXD+j];
        e0 += w * vf[o*ND+lane];
        e1 += w * vf[o*ND+lane+32];
        e2 += w * vf[o*ND+lane+64];
        e3 += w * vf[o*ND+lane+96];
    }
    float qk = 0.f;
#pragma unroll
    for (int k = 0; k < PQ; k++) {
        float s = warp_sum(e0*Wq[lane*PQ+k] + e1*Wq[(lane+32)*PQ+k] +
                           e2*Wq[(lane+64)*PQ+k] + e3*Wq[(lane+96)*PQ+k]);
        if (lane == k) qk = tanhf(s + bq[k]);
    }
    float qd0 = warp_sum(lane < PQ ? qk * Wu[ND+lane] : 0.f);
    if (lane < PQ) g_q0[n*PQ+lane] = qk;
    if (lane == 0) g_qd0[n] = qd0;
}

// ======== k4: 4 layers on scalar state; 512 threads => 128-reg budget, NO spills ========
#define K4_SMEM (INC_CAP*2 + INC_CAP*4 + 7*Nn*4 + 8*Mm*4 + 2*Mm*4 + 64*4 + 40*4 + 32*4)
__global__ void __launch_bounds__(K4T, 1)
k4(const float* __restrict__ Wt, const float* __restrict__ Wu, float* __restrict__ out)
{
    extern __shared__ char sm_raw[];
    unsigned short* s_o = (unsigned short*)sm_raw;          // INC_CAP
    float* s_w    = (float*)(s_o + INC_CAP);                // INC_CAP
    float* s_cumA = s_w + INC_CAP;                          // Nn
    float* s_cumB = s_cumA + Nn;                            // Nn
    float* s_su   = s_cumB + Nn;                            // Nn (prologue: qd0 temp)
    float* s_zub  = s_su + Nn;                              // Nn
    float* s_atp  = s_zub + Nn;                             // Nn  (avt + pd0)
    float* s_pd0  = s_atp + Nn;                             // Nn
    float* s_pwu  = s_pd0 + Nn;                             // Nn
    float* s_Gm   = s_pwu + Nn;                             // 4*Mm
    float* s_Sm   = s_Gm + 4*Mm;                            // 4*Mm
    float* s_h    = s_Sm + 4*Mm;                            // Mm
    float* s_d2   = s_h + Mm;                               // Mm
    float* s_red  = s_d2 + Mm;                              // 64
    float* s_slT  = s_red + 64;                             // 40
    int*   s_ib   = (int*)(s_slT + 40);                     // 32

    const int t = threadIdx.x, lane = t & 31, wp = t >> 5;  // wp in [0,16)

    float nWt = 0.f, nWu = 0.f, dTU = 0.f;
#pragma unroll
    for (int k = 0; k < PQ; k++) {
        float a = Wu[ND+k], b = Wt[ND+k];
        nWu += a*a; nWt += b*b; dTU += a*b;
    }

    for (int i = t; i < 4*Mm; i += K4T) { s_Gm[i] = 0.f; s_Sm[i] = 0.f; }
    if (t < Mm) { s_h[t] = 0.f; s_d2[t] = 0.f; }

    // ---- degree scan -> CSR offsets ----
    int deg[K4J], off[K4J], end_[K4J];
    int tot = 0;
#pragma unroll
    for (int j = 0; j < K4J; j++) { deg[j] = min(g_cnt[t + j*K4T], MAXD); tot += deg[j]; }
    int pre = tot;
#pragma unroll
    for (int o = 1; o < 32; o <<= 1) { int v = __shfl_up_sync(0xffffffffu, pre, o); if (lane >= o) pre += v; }
    if (lane == 31) s_ib[wp] = pre;
    __syncthreads();
    if (wp == 0) {
        int v = (lane < K4W) ? s_ib[lane] : 0;
        int p2 = v;
#pragma unroll
        for (int o = 1; o < 32; o <<= 1) { int x = __shfl_up_sync(0xffffffffu, p2, o); if (lane >= o) p2 += x; }
        if (lane < K4W) s_ib[lane] = p2 - v;
    }
    __syncthreads();
    {
        int base = s_ib[wp] + (pre - tot);
#pragma unroll
        for (int j = 0; j < K4J; j++) { off[j] = base; base += deg[j]; end_[j] = base; }
    }

    // ---- compact incidences + load node statics; qd0 into s_su temporarily ----
    int   mol[K4J];
    float Wn[K4J];
    float pnsum = 0.f;
#pragma unroll
    for (int j = 0; j < K4J; j++) {
        int n = t + j*K4T;
        Wn[j] = g_Wn[n]; mol[j] = g_mol[n];
        float pd0 = g_pd0[n];
        s_su[n]  = g_qd0[n];
        s_atp[n] = g_avt[n] + pd0;
        s_pd0[n] = pd0;
        s_pwu[n] = g_pwu[n];
        s_cumA[n] = 0.f;
        pnsum += g_pn[n];
        for (int x = 0; x < deg[j]; x++) {
            s_o[off[j]+x] = (unsigned short)(g_adj[n*MAXD+x] & 0xFFF);
            s_w[off[j]+x] = g_winc[n*MAXD+x];
        }
    }
    pnsum = warp_sum(pnsum);
    if (lane == 0) s_red[wp] = pnsum;
    __syncthreads();
    if (t == 0) {
        float s = 0.f;
        for (int i = 0; i < K4W; i++) s += s_red[i];
        s_slT[LAYERS] = s;
    }
    __syncthreads();

    // ---- zub = avu + Wn*qd0 + sum w*qd0[o] ----
#pragma unroll
    for (int j = 0; j < K4J; j++) {
        int n = t + j*K4T;
        float g = Wn[j] * s_su[n];
        for (int x = off[j]; x < end_[j]; x++) g += s_w[x] * s_su[s_o[x]];
        s_zub[n] = g_avu[n] + g;
    }
    __syncthreads();

    // ---- layers (i rolled; j fully unrolled so arrays stay in registers) ----
    float cumGg[K4J], wS[K4J], wG[K4J];
#pragma unroll
    for (int j = 0; j < K4J; j++) { cumGg[j] = 0.f; wS[j] = 0.f; wG[j] = 0.f; }
    float* cur = s_cumA;
    float* nxt = s_cumB;
    for (int i = 0; i < LAYERS; i++) {
        // phase a: gather cumSt -> st, su
#pragma unroll
        for (int j = 0; j < K4J; j++) {
            int n = t + j*K4T;
            float cA = cur[n];
            float g = Wn[j] * cA;
            for (int x = off[j]; x < end_[j]; x++) g += s_w[x] * cur[s_o[x]];
            float zu = s_zub[n] + TAU * dTU * g;
            float zt = s_atp[n] - TAU * (dTU * cumGg[j] + FRIC * nWt * cA);
            float st = sigmoidf(zt), su = sigmoidf(zu);
            s_su[n] = su;
            nxt[n] = cA + st;
            atomicAdd(&s_Sm[i*Mm + mol[j]], st);
            if (i == LAYERS-1) {
                atomicAdd(&s_h[mol[j]], softplusf(zt) + softplusf(zu));
                atomicAdd(&s_d2[mol[j]], st * st);
            }
        }
        __syncthreads();
        // phase b: gather su -> gg, losses, weighted sums
        float slp = 0.f;
        const float lw = (float)(LAYERS - i);
#pragma unroll
        for (int j = 0; j < K4J; j++) {
            int n = t + j*K4T;
            float su = s_su[n];
            float cA = cur[n];
            float st = nxt[n] - cA;
            float gg = Wn[j] * su;
            for (int x = off[j]; x < end_[j]; x++) gg += s_w[x] * s_su[s_o[x]];
            float alpha = st + TAU * FRIC * cA;
            float beta  = TAU * cumGg[j];
            slp += alpha*alpha*nWt + beta*beta*nWu + 2.f*alpha*beta*dTU
                 - 2.f*alpha*s_pd0[n] - 2.f*beta*s_pwu[n];
            atomicAdd(&s_Gm[i*Mm + mol[j]], gg);
            cumGg[j] += gg;
            wS[j] += lw * st;
            wG[j] += lw * gg;
        }
        // per-layer s-loss reduction inside the existing sync window
        slp = warp_sum(slp);
        if (lane == 0) s_red[wp] = slp;
        __syncthreads();
        if (wp == 0) {
            float v = warp_sum(lane < K4W ? s_red[lane] : 0.f);
            if (lane == 0) s_slT[i] = v + s_slT[LAYERS];
        }
        float* tmp = cur; cur = nxt; nxt = tmp;
    }
    __syncthreads();   // protect s_slT[LAYERS-1] before the t<32 read below

    // ---- write final-average coefficients ----
#pragma unroll
    for (int j = 0; j < K4J; j++) {
        int n = t + j*K4T;
        g_SA[n] = -(TAU*FRIC) * wS[j];
        g_SB[n] = -TAU * wG[j];
        g_SC[n] =  TAU * wS[j];
    }

    if (t < 32) {
        float cT = 0.f;
        for (int i = 0; i < LAYERS; i++) {
            float term = 0.f;
            for (int m = lane; m < Mm; m += 32) {
                float Gm = s_Gm[i*Mm+m], Sm = s_Sm[i*Mm+m];
                term += Gm*Gm*nWu + 2.f*FRIC*Gm*Sm*dTU + FRIC*FRIC*Sm*Sm*nWt;
            }
            term = warp_sum(term);
            cT += TAU * sqrtf(term);
        }
        if (lane == 0) {
            float sT = 0.f;
            for (int i = 0; i < LAYERS; i++) sT += sqrtf(s_slT[i]);
            out[2*NP + 0] = sT;
            out[2*NP + 1] = cT;
        }
    }
    if (t < Mm) {
        out[2*NP + 2 + t]      = s_h[t];
        out[2*NP + 2 + Mm + t] = s_d2[t] * nWt;
    }
}

// ======== k5: expand outputs, reset counters ========
__global__ void k5(const float* __restrict__ Wt, const float* __restrict__ Wu,
                   float* __restrict__ out)
{
    int idx = blockIdx.x * blockDim.x + threadIdx.x;  // 131072 = 2*NP
    if (idx < NP) {
        int n = idx >> 4, k = idx & 15;
        out[idx] = 0.2f * (5.f*g_p0[idx] + g_SA[n]*Wt[ND+k] + g_SB[n]*Wu[ND+k]);
    } else {
        int id2 = idx - NP, n = id2 >> 4, k = id2 & 15;
        out[idx] = 0.2f * (5.f*g_q0[id2] + g_SC[n]*Wt[ND+k]);
    }
    if (idx < Nn) g_cnt[idx] = 0;
}

extern "C" void kernel_launch(void* const* d_in, const int* in_sizes, int n_in,
                              void* d_out, int out_size)
{
    const float* vf  = (const float*)d_in[0];
    const float* ef  = (const float*)d_in[1];
    const int*   us  = (const int*)  d_in[2];
    const int*   vs  = (const int*)  d_in[3];
    const float* mnm = (const float*)d_in[4];
    const float* We  = (const float*)d_in[8];
    const float* be  = (const float*)d_in[9];
    const float* Wp  = (const float*)d_in[10];
    const float* bp  = (const float*)d_in[11];
    const float* Wq  = (const float*)d_in[12];
    const float* bq  = (const float*)d_in[13];
    const float* Wt  = (const float*)d_in[14];
    const float* Wu  = (const float*)d_in[15];
    float* out = (float*)d_out;

    cudaFuncSetAttribute(k4, cudaFuncAttributeMaxDynamicSharedMemorySize, K4_SMEM);

    k1<<<512, 256>>>(vf, mnm, us, vs, We, Wp, bp, Wt, Wu);
    k2<<<1024, 256>>>(ef, us, vs, We, be);
    k3<<<512, 256>>>(vf, Wq, bq, Wu);
    k4<<<1, K4T, K4_SMEM>>>(Wt, Wu, out);
    k5<<<512, 256>>>(Wt, Wu, out);
}

// round 8
// speedup vs baseline: 1.7042x; 1.7042x over previous
#include <cuda_runtime.h>
#include <math.h>

#define Nn 4096
#define Ee 8192
#define Mm 128
#define ND 128
#define ED 64
#define PQ 16
#define NP (Nn*PQ)
#define LAYERS 4
#define TAU 0.25f
#define FRIC 0.1f
#define MAXD 32

// ---------------- device scratch (no allocation allowed) ----------------
__device__ float g_a[Nn], g_c[Nn], g_avt[Nn], g_avu[Nn];
__device__ float g_pd0[Nn], g_pwu[Nn], g_pn[Nn], g_qd0[Nn], g_Wn[Nn];
__device__ int   g_mol[Nn];
__device__ int   g_cnt[Nn];            // zero at k1 entry; reset in kF
__device__ int   g_adj[Nn * MAXD];     // (e<<12)|other
__device__ float g_winc[Nn * MAXD];
__device__ int   g_slotU[Ee], g_slotV[Ee];
__device__ float g_p0[NP], g_q0[NP];
__device__ float g_suA[Nn], g_suB[Nn], g_cumA[Nn], g_cumB[Nn], g_cumG[Nn];
__device__ float g_stv[Nn], g_zubA[Nn], g_atpA[Nn], g_wS[Nn], g_wG[Nn];
__device__ float g_Gm[LAYERS*Mm], g_Sm[LAYERS*Mm], g_h[Mm], g_d[Mm], g_S[LAYERS];

__device__ __forceinline__ float warp_sum(float v) {
#pragma unroll
    for (int o = 16; o; o >>= 1) v += __shfl_xor_sync(0xffffffffu, v, o);
    return v;
}
__device__ __forceinline__ float sigmoidf(float x) { return 1.f / (1.f + expf(-x)); }
__device__ __forceinline__ float softplusf(float x) { return fmaxf(x, 0.f) + log1pf(expf(-fabsf(x))); }

// ======== k1: node setup (warp/node) + mol ids + adjacency + accumulator zeroing ========
__global__ void k1(const float* __restrict__ vf, const float* __restrict__ mnm,
                   const int* __restrict__ us, const int* __restrict__ vs,
                   const float* __restrict__ We, const float* __restrict__ Wp,
                   const float* __restrict__ bp, const float* __restrict__ Wt,
                   const float* __restrict__ Wu)
{
    int tid  = blockIdx.x * blockDim.x + threadIdx.x;   // 131072 threads
    int lane = threadIdx.x & 31;
    int n    = tid >> 5;                                 // warp -> node

    if (tid < Nn) g_Wn[tid] = 0.f;
    if (tid < LAYERS*Mm) { g_Gm[tid] = 0.f; g_Sm[tid] = 0.f; }
    if (tid < Mm) { g_h[tid] = 0.f; g_d[tid] = 0.f; }
    if (tid < LAYERS) g_S[tid] = 0.f;

    for (int idx = tid; idx < Mm * Nn; idx += 131072)
        if (mnm[idx] > 0.5f) g_mol[idx & (Nn - 1)] = idx >> 12;

    for (int e = tid; e < Ee; e += 131072) {
        int u = us[e], v = vs[e];
        int s1 = atomicAdd(&g_cnt[u], 1);
        if (s1 < MAXD) g_adj[u * MAXD + s1] = (e << 12) | v;
        g_slotU[e] = s1;
        if (u != v) {
            int s2 = atomicAdd(&g_cnt[v], 1);
            if (s2 < MAXD) g_adj[v * MAXD + s2] = (e << 12) | u;
            g_slotV[e] = s2;
        }
    }

    float v0 = vf[n*ND+lane], v1 = vf[n*ND+lane+32], v2 = vf[n*ND+lane+64], v3 = vf[n*ND+lane+96];
    float sa = warp_sum(v0*We[lane]     + v1*We[lane+32]     + v2*We[lane+64]     + v3*We[lane+96]);
    float sc = warp_sum(v0*We[192+lane] + v1*We[192+lane+32] + v2*We[192+lane+64] + v3*We[192+lane+96]);
    float st = warp_sum(v0*Wt[lane]     + v1*Wt[lane+32]     + v2*Wt[lane+64]     + v3*Wt[lane+96]);
    float su = warp_sum(v0*Wu[lane]     + v1*Wu[lane+32]     + v2*Wu[lane+64]     + v3*Wu[lane+96]);

    float pk = 0.f;
#pragma unroll
    for (int k = 0; k < PQ; k++) {
        float s = warp_sum(v0*Wp[lane*PQ+k] + v1*Wp[(lane+32)*PQ+k] +
                           v2*Wp[(lane+64)*PQ+k] + v3*Wp[(lane+96)*PQ+k]);
        if (lane == k) pk = tanhf(s + bp[k]);
    }
    float pd0 = warp_sum(lane < PQ ? pk * Wt[ND+lane] : 0.f);
    float pwu = warp_sum(lane < PQ ? pk * Wu[ND+lane] : 0.f);
    float pn  = warp_sum(lane < PQ ? pk * pk          : 0.f);
    if (lane < PQ) g_p0[n*PQ+lane] = pk;
    if (lane == 0) {
        g_a[n] = sa; g_c[n] = sc; g_avt[n] = st; g_avu[n] = su;
        g_pd0[n] = pd0; g_pwu[n] = pwu; g_pn[n] = pn;
    }
}

// ======== k2: edge weights (warp/edge) ========
__global__ void k2(const float* __restrict__ ef,
                   const int* __restrict__ us, const int* __restrict__ vs,
                   const float* __restrict__ We, const float* __restrict__ be)
{
    int e    = (blockIdx.x * blockDim.x + threadIdx.x) >> 5;
    int lane = threadIdx.x & 31;
    if (e >= Ee) return;
    float s = ef[e*ED+lane] * We[128+lane] + ef[e*ED+32+lane] * We[160+lane];
    s = warp_sum(s);
    if (lane == 0) {
        int u = us[e], v = vs[e];
        float w = sigmoidf(g_a[u] + g_c[v] + s + be[0]);
        int s1 = g_slotU[e];
        if (s1 < MAXD) g_winc[u * MAXD + s1] = w;
        if (u != v) {
            int s2 = g_slotV[e];
            if (s2 < MAXD) g_winc[v * MAXD + s2] = w;
            atomicAdd(&g_Wn[u], w);
            atomicAdd(&g_Wn[v], w);
        }
    }
}

// ======== k3: q0 = tanh((e@v)@Wq + bq), qd0 (warp/node) ========
__global__ void k3(const float* __restrict__ vf, const float* __restrict__ Wq,
                   const float* __restrict__ bq, const float* __restrict__ Wu)
{
    int n    = (blockIdx.x * blockDim.x + threadIdx.x) >> 5;
    int lane = threadIdx.x & 31;
    float x0 = vf[n*ND+lane], x1 = vf[n*ND+lane+32], x2 = vf[n*ND+lane+64], x3 = vf[n*ND+lane+96];
    float Wn = g_Wn[n];
    float e0 = Wn*x0, e1 = Wn*x1, e2 = Wn*x2, e3 = Wn*x3;
    int deg = min(g_cnt[n], MAXD);
    for (int j = 0; j < deg; j++) {
        int   o = g_adj[n*MAXD+j] & 0xFFF;
        float w = g_winc[n*MAXD+j];
        e0 += w * vf[o*ND+lane];
        e1 += w * vf[o*ND+lane+32];
        e2 += w * vf[o*ND+lane+64];
        e3 += w * vf[o*ND+lane+96];
    }
    float qk = 0.f;
#pragma unroll
    for (int k = 0; k < PQ; k++) {
        float s = warp_sum(e0*Wq[lane*PQ+k] + e1*Wq[(lane+32)*PQ+k] +
                           e2*Wq[(lane+64)*PQ+k] + e3*Wq[(lane+96)*PQ+k]);
        if (lane == k) qk = tanhf(s + bq[k]);
    }
    float qd0 = warp_sum(lane < PQ ? qk * Wu[ND+lane] : 0.f);
    if (lane < PQ) g_q0[n*PQ+lane] = qk;
    if (lane == 0) g_qd0[n] = qd0;
}

// ======== kZ: zub gather + layer-1 locals (thread/node, 4096 threads) ========
__global__ void kZ(const float* __restrict__ Wt)
{
    int n = blockIdx.x * blockDim.x + threadIdx.x;
    float nWt = 0.f;
#pragma unroll
    for (int k = 0; k < PQ; k++) { float b = Wt[ND+k]; nWt += b*b; }

    int deg = min(g_cnt[n], MAXD);
    float s = g_Wn[n] * g_qd0[n];
    for (int j = 0; j < deg; j++) {
        int o = g_adj[n*MAXD+j] & 0xFFF;
        s += g_winc[n*MAXD+j] * g_qd0[o];
    }
    float zub = g_avu[n] + s;
    float atp = g_avt[n] + g_pd0[n];
    g_zubA[n] = zub; g_atpA[n] = atp;

    float st1 = sigmoidf(atp), su1 = sigmoidf(zub);
    g_suA[n] = su1; g_cumA[n] = st1; g_stv[n] = st1;
    g_wS[n] = 4.f * st1;
    atomicAdd(&g_Sm[g_mol[n]], st1);

    float sl = st1*st1*nWt - 2.f*st1*g_pd0[n];
    sl = warp_sum(sl);
    __shared__ float sh[8];
    if ((threadIdx.x & 31) == 0) sh[threadIdx.x >> 5] = sl;
    __syncthreads();
    if (threadIdx.x == 0) {
        float t = 0.f;
        for (int i = 0; i < 8; i++) t += sh[i];
        atomicAdd(&g_S[0], t);
    }
}

// ======== kL: one layer phase (ph=1..4); gathers (su_ph, cumSt_ph) ========
__global__ void kL(const float* __restrict__ Wt, const float* __restrict__ Wu, int ph)
{
    int n = blockIdx.x * blockDim.x + threadIdx.x;
    float nWt = 0.f, nWu = 0.f, dTU = 0.f;
#pragma unroll
    for (int k = 0; k < PQ; k++) {
        float a = Wu[ND+k], b = Wt[ND+k];
        nWu += a*a; nWt += b*b; dTU += a*b;
    }
    const float* suIN  = (ph & 1) ? g_suA  : g_suB;
    float*       suOUT = (ph & 1) ? g_suB  : g_suA;
    const float* cumIN = (ph & 1) ? g_cumA : g_cumB;
    float*       cumOUT= (ph & 1) ? g_cumB : g_cumA;

    int deg = min(g_cnt[n], MAXD);
    float Wn = g_Wn[n];
    float suSelf = suIN[n], cumSelf = cumIN[n];
    float gg = Wn * suSelf, G = Wn * cumSelf;
    for (int j = 0; j < deg; j++) {
        int   o = g_adj[n*MAXD+j] & 0xFFF;
        float w = g_winc[n*MAXD+j];
        gg += w * suIN[o];
        G  += w * cumIN[o];
    }
    int mol = g_mol[n];
    atomicAdd(&g_Gm[(ph-1)*Mm + mol], gg);
    float cumG = ((ph == 1) ? 0.f : g_cumG[n]) + gg;
    g_cumG[n] = cumG;
    if (ph == 1) g_wG[n] = 4.f * gg;
    else         g_wG[n] += (float)(5 - ph) * gg;

    float sl = 0.f;
    if (ph < 4) {
        float zt = g_atpA[n] - TAU * (dTU * cumG + FRIC * nWt * cumSelf);
        float st = sigmoidf(zt);
        float zu = g_zubA[n] + TAU * dTU * G;
        float su = sigmoidf(zu);
        suOUT[n] = su;
        cumOUT[n] = cumSelf + st;
        g_stv[n] = st;
        g_wS[n] += (float)(4 - ph) * st;
        atomicAdd(&g_Sm[ph*Mm + mol], st);
        float alpha = st + TAU * FRIC * cumSelf;
        float beta  = TAU * cumG;
        sl = alpha*alpha*nWt + beta*beta*nWu + 2.f*alpha*beta*dTU
           - 2.f*alpha*g_pd0[n] - 2.f*beta*g_pwu[n];
        if (ph == 3) {   // zt/zu/st here are layer-4 values
            atomicAdd(&g_h[mol], softplusf(zt) + softplusf(zu));
            atomicAdd(&g_d[mol], st * st);
        }
    }
    // per-layer s-loss reduce (layer ph+1 -> g_S[ph]); ph==4 contributes nothing
    sl = warp_sum(sl);
    __shared__ float sh[8];
    if ((threadIdx.x & 31) == 0) sh[threadIdx.x >> 5] = sl;
    __syncthreads();
    if (threadIdx.x == 0 && ph < 4) {
        float t = 0.f;
        for (int i = 0; i < 8; i++) t += sh[i];
        atomicAdd(&g_S[ph], t);
    }
}

// ======== kF: outputs + scalars + counter reset ========
__global__ void kF(const float* __restrict__ Wt, const float* __restrict__ Wu,
                   float* __restrict__ out)
{
    int idx = blockIdx.x * blockDim.x + threadIdx.x;  // 131072 = 2*NP
    if (idx < NP) {
        int n = idx >> 4, k = idx & 15;
        out[idx] = 0.2f * (5.f*g_p0[idx] - (TAU*FRIC)*g_wS[n]*Wt[ND+k] - TAU*g_wG[n]*Wu[ND+k]);
    } else {
        int id2 = idx - NP, n = id2 >> 4, k = id2 & 15;
        out[idx] = 0.2f * (5.f*g_q0[id2] + TAU*g_wS[n]*Wt[ND+k]);
    }
    if (idx < Nn) g_cnt[idx] = 0;

    if (blockIdx.x == 0) {
        int t = threadIdx.x, lane = t & 31;
        float nWt = 0.f, nWu = 0.f, dTU = 0.f;
#pragma unroll
        for (int k = 0; k < PQ; k++) {
            float a = Wu[ND+k], b = Wt[ND+k];
            nWu += a*a; nWt += b*b; dTU += a*b;
        }
        // PN = sum of ||p0||^2 over nodes
        __shared__ float sh[8];
        __shared__ float shPN;
        float pn = 0.f;
        for (int n = t; n < Nn; n += 256) pn += g_pn[n];
        pn = warp_sum(pn);
        if (lane == 0) sh[t >> 5] = pn;
        __syncthreads();
        if (t == 0) {
            float s = 0.f;
            for (int i = 0; i < 8; i++) s += sh[i];
            shPN = s;
        }
        __syncthreads();
        if (t < 32) {
            float cT = 0.f;
            for (int i = 0; i < LAYERS; i++) {
                float term = 0.f;
                for (int m = lane; m < Mm; m += 32) {
                    float Gm = g_Gm[i*Mm+m], Sm = g_Sm[i*Mm+m];
                    term += Gm*Gm*nWu + 2.f*FRIC*Gm*Sm*dTU + FRIC*FRIC*Sm*Sm*nWt;
                }
                term = warp_sum(term);
                cT += TAU * sqrtf(term);
            }
            if (lane == 0) {
                float sT = 0.f;
                for (int i = 0; i < LAYERS; i++) sT += sqrtf(g_S[i] + shPN);
                out[2*NP + 0] = sT;
                out[2*NP + 1] = cT;
            }
        }
        if (t < Mm) {
            out[2*NP + 2 + t]      = g_h[t];
            out[2*NP + 2 + Mm + t] = g_d[t] * nWt;
        }
    }
}

extern "C" void kernel_launch(void* const* d_in, const int* in_sizes, int n_in,
                              void* d_out, int out_size)
{
    const float* vf  = (const float*)d_in[0];
    const float* ef  = (const float*)d_in[1];
    const int*   us  = (const int*)  d_in[2];
    const int*   vs  = (const int*)  d_in[3];
    const float* mnm = (const float*)d_in[4];
    const float* We  = (const float*)d_in[8];
    const float* be  = (const float*)d_in[9];
    const float* Wp  = (const float*)d_in[10];
    const float* bp  = (const float*)d_in[11];
    const float* Wq  = (const float*)d_in[12];
    const float* bq  = (const float*)d_in[13];
    const float* Wt  = (const float*)d_in[14];
    const float* Wu  = (const float*)d_in[15];
    float* out = (float*)d_out;

    k1<<<512, 256>>>(vf, mnm, us, vs, We, Wp, bp, Wt, Wu);
    k2<<<1024, 256>>>(ef, us, vs, We, be);
    k3<<<512, 256>>>(vf, Wq, bq, Wu);
    kZ<<<16, 256>>>(Wt);
    kL<<<16, 256>>>(Wt, Wu, 1);
    kL<<<16, 256>>>(Wt, Wu, 2);
    kL<<<16, 256>>>(Wt, Wu, 3);
    kL<<<16, 256>>>(Wt, Wu, 4);
    kF<<<512, 256>>>(Wt, Wu, out);
}